// round 15
// baseline (speedup 1.0000x reference)
#include <cuda_runtime.h>
#include <cuda_fp16.h>
#include <cstdint>

// Problem: B=4,S=4096 -> T=16384 tokens; IN_F=OUT_F=4096; G=32; GS=GO=128.
// y[t, g*128+n] = sum_k x[t, perm[g*128+k]] * W[g,n,k] + b[g,n]
// Numerics: x -> fp16, W -> fp16 hi + lo; y = xh*Wh + xh*Wl, f32 accum.
#define IN_F   4096
#define G      32
#define TMAX   16384
#define TILE_T 128
#define NCHUNK 8

// ---------------- device scratch (static; no allocation) ----------------
__device__ int      g_perm[IN_F];
__device__ uint32_t g_whf[64 * 4096];     // W hi fragments per half-group (fp16x2)
__device__ uint32_t g_wlf[64 * 4096];     // W lo fragments (fp16x2)
// Pre-swizzled fp16 A tiles: [ttile=128][g=32][32KB tile]
__device__ unsigned char g_xt[(size_t)128 * 32 * 32768];

__device__ __forceinline__ uint32_t smem_u32(const void* p) {
    uint32_t a;
    asm("{ .reg .u64 t; cvta.to.shared.u64 t, %1; cvt.u32.u64 %0, t; }" : "=r"(a) : "l"(p));
    return a;
}

__device__ __forceinline__ uint32_t pack_h2(float lo, float hi) {
    __half2 h = __floats2half2_rn(lo, hi);   // lo -> low 16 bits
    return *(uint32_t*)&h;
}

// ---------------- pass 0a: normalize perm (int64-or-int32 -> int32) ----------------
__global__ void convert_perm_kernel(const int* __restrict__ p32) {
    __shared__ int is64;
    if (threadIdx.x == 0) {
        int all0 = 1;
        #pragma unroll
        for (int i = 1; i < 16; i += 2) all0 &= (p32[i] == 0);
        is64 = all0;
    }
    __syncthreads();
    const int w = is64;
    for (int i = threadIdx.x; i < IN_F; i += blockDim.x)
        g_perm[i] = w ? p32[2 * i] : p32[i];
}

// ---------------- pass 0b: W -> fp16 hi/lo, LDS.64-friendly fragment order --------
// e = ((((wn*8 + ks)*4 + nt)*32) + lane)*2 + r
//   n  = (hg&1)*64 + wn*32 + nt*8 + lane/4 ; k0 = ks*16 + 2*(lane&3) + r*8
__global__ void wprep_kernel(const float* __restrict__ W) {
    const int hg = blockIdx.x;            // 0..63
    const int g = hg >> 1;
    for (int e = threadIdx.x; e < 4096; e += blockDim.x) {
        const int r    = e & 1;
        const int lane = (e >> 1) & 31;
        const int nt   = (e >> 6) & 3;
        const int ks   = (e >> 8) & 7;
        const int wn   = e >> 11;
        const int n    = (hg & 1) * 64 + wn * 32 + nt * 8 + (lane >> 2);
        const int k0   = ks * 16 + 2 * (lane & 3) + r * 8;
        const float v0 = W[((size_t)g * 128 + n) * 128 + k0];
        const float v1 = W[((size_t)g * 128 + n) * 128 + k0 + 1];
        const float h0 = __half2float(__float2half_rn(v0));
        const float h1 = __half2float(__float2half_rn(v1));
        g_whf[hg * 4096 + e] = pack_h2(h0, h1);
        g_wlf[hg * 4096 + e] = pack_h2(v0 - h0, v1 - h1);
    }
}

// ---------------- pass 1: permute + fp16 convert into GEMM-ready tiles ----------------
// Block: 8 tokens, 256 threads, 64 KB smem fp16 rows.
__global__ __launch_bounds__(256) void xprep_kernel(const float* __restrict__ x, int tok0) {
    extern __shared__ unsigned short rows16[];      // 8 * 4096 fp16 = 64 KB
    const int t0    = tok0 + blockIdx.x * 8;
    const int ttile = t0 >> 7;
    const int tbase = t0 & 127;
    const int tid = threadIdx.x, lane = tid & 31, wid = tid >> 5;

    {
        const float4* src = (const float4*)(x + (size_t)t0 * IN_F);
        uint2* r2 = (uint2*)rows16;
        #pragma unroll 8
        for (int i = tid; i < 8192; i += 256) {
            const float4 v = src[i];
            r2[i] = make_uint2(pack_h2(v.x, v.y), pack_h2(v.z, v.w));
        }
    }
    __syncthreads();

    const int q       = lane & 15;                  // 16B chunk within row
    const int half_id = wid * 2 + (lane >> 4);      // 0..15

    #pragma unroll 4
    for (int it = 0; it < 16; ++it) {
        const int rt  = it * 16 + half_id;          // 0..255
        const int tok = rt >> 5;                    // 0..7
        const int g   = rt & 31;
        const unsigned short* row = rows16 + tok * IN_F;

        const int4* pp = (const int4*)(g_perm + g * 128 + 8 * q);
        const int4 pa = pp[0];
        const int4 pb = pp[1];

        uint4 v;
        v.x = (uint32_t)row[pa.x] | ((uint32_t)row[pa.y] << 16);
        v.y = (uint32_t)row[pa.z] | ((uint32_t)row[pa.w] << 16);
        v.z = (uint32_t)row[pb.x] | ((uint32_t)row[pb.y] << 16);
        v.w = (uint32_t)row[pb.z] | ((uint32_t)row[pb.w] << 16);

        const uint32_t t   = (uint32_t)(tbase + tok);
        const uint32_t off = t * 256 + (((uint32_t)q ^ (t & 7)) << 4);
        *(uint4*)(g_xt + ((size_t)ttile * 32 + g) * 32768 + off) = v;
    }
}

// ---------------- pass 2: HMMA block-diagonal GEMM, all-smem mainloop ------------
// CTA: 128 tokens x 64 outputs (half-group), 128 threads, warp grid 2x2,
// warp tile 64x32. Prologue cp.asyncs A (32KB) + B hi/lo (32KB); mainloop
// touches ONLY smem (ldmatrix + LDS.64) + HMMA. 3 CTA/SM.
#define SM_A   0
#define SM_BH  32768
#define SM_BL  49152
#define SM_SZ  65536

__global__ __launch_bounds__(128, 3)
void bdl_mma_kernel(const float* __restrict__ bias, float* __restrict__ out, int tt0)
{
    extern __shared__ char smem[];
    const uint32_t sb = smem_u32(smem);
    const int hg = blockIdx.x;
    const int g  = hg >> 1;
    const int ttile = tt0 + blockIdx.y;
    const int t0 = ttile * TILE_T;
    const int tid = threadIdx.x, lane = tid & 31, wid = tid >> 5;

    // --- prologue: A tile + B hi/lo via cp.async, one wait ---
    {
        const unsigned char* sa = g_xt + ((size_t)ttile * 32 + g) * 32768;
        #pragma unroll 4
        for (int e = tid; e < 2048; e += 128)
            asm volatile("cp.async.cg.shared.global [%0], [%1], 16;"
                         :: "r"(sb + SM_A + e * 16), "l"(sa + e * 16));
        const unsigned char* bh = (const unsigned char*)(g_whf + hg * 4096);
        const unsigned char* bl = (const unsigned char*)(g_wlf + hg * 4096);
        #pragma unroll 4
        for (int e = tid; e < 1024; e += 128) {
            asm volatile("cp.async.cg.shared.global [%0], [%1], 16;"
                         :: "r"(sb + SM_BH + e * 16), "l"(bh + e * 16));
            asm volatile("cp.async.cg.shared.global [%0], [%1], 16;"
                         :: "r"(sb + SM_BL + e * 16), "l"(bl + e * 16));
        }
        asm volatile("cp.async.commit_group;");
        asm volatile("cp.async.wait_group 0;");
    }
    __syncthreads();

    const int wm = wid & 1;
    const int wn = wid >> 1;

    const uint32_t bh_base = sb + SM_BH + (uint32_t)wn * 8192 + (uint32_t)lane * 8;
    const uint32_t bl_base = sb + SM_BL + (uint32_t)wn * 8192 + (uint32_t)lane * 8;

    float acc[4][4][4];
    #pragma unroll
    for (int mt = 0; mt < 4; ++mt)
        #pragma unroll
        for (int nt = 0; nt < 4; ++nt)
            #pragma unroll
            for (int q = 0; q < 4; ++q) acc[mt][nt][q] = 0.0f;

    #pragma unroll
    for (int ks = 0; ks < 8; ++ks) {
        uint32_t bh[4][2], bl[4][2];
        #pragma unroll
        for (int nt = 0; nt < 4; ++nt) {
            const uint32_t soff = (uint32_t)(ks * 4 + nt) * 256;
            asm volatile("ld.shared.v2.b32 {%0,%1}, [%2];"
                         : "=r"(bh[nt][0]), "=r"(bh[nt][1]) : "r"(bh_base + soff));
            asm volatile("ld.shared.v2.b32 {%0,%1}, [%2];"
                         : "=r"(bl[nt][0]), "=r"(bl[nt][1]) : "r"(bl_base + soff));
        }

        uint32_t ah[4][4];
        #pragma unroll
        for (int mt = 0; mt < 4; ++mt) {
            const uint32_t row = (uint32_t)(wm * 64 + mt * 16 + (lane & 15));
            const uint32_t c   = (uint32_t)(2 * ks + (lane >> 4));
            const uint32_t aoff = row * 256 + ((c ^ (row & 7)) << 4);
            asm volatile("ldmatrix.sync.aligned.m8n8.x4.shared.b16 {%0,%1,%2,%3}, [%4];"
                         : "=r"(ah[mt][0]), "=r"(ah[mt][1]), "=r"(ah[mt][2]), "=r"(ah[mt][3])
                         : "r"(sb + SM_A + aoff));
        }
        #pragma unroll
        for (int mt = 0; mt < 4; ++mt)
            #pragma unroll
            for (int nt = 0; nt < 4; ++nt) {
                asm volatile(
                    "mma.sync.aligned.m16n8k16.row.col.f32.f16.f16.f32 "
                    "{%0,%1,%2,%3}, {%4,%5,%6,%7}, {%8,%9}, {%0,%1,%2,%3};"
                    : "+f"(acc[mt][nt][0]), "+f"(acc[mt][nt][1]),
                      "+f"(acc[mt][nt][2]), "+f"(acc[mt][nt][3])
                    : "r"(ah[mt][0]), "r"(ah[mt][1]), "r"(ah[mt][2]), "r"(ah[mt][3]),
                      "r"(bh[nt][0]), "r"(bh[nt][1]));
                asm volatile(
                    "mma.sync.aligned.m16n8k16.row.col.f32.f16.f16.f32 "
                    "{%0,%1,%2,%3}, {%4,%5,%6,%7}, {%8,%9}, {%0,%1,%2,%3};"
                    : "+f"(acc[mt][nt][0]), "+f"(acc[mt][nt][1]),
                      "+f"(acc[mt][nt][2]), "+f"(acc[mt][nt][3])
                    : "r"(ah[mt][0]), "r"(ah[mt][1]), "r"(ah[mt][2]), "r"(ah[mt][3]),
                      "r"(bl[nt][0]), "r"(bl[nt][1]));
            }
    }

    // --- epilogue: bias + st.v2 (c-fragment layout) ---
    const int colbase = g * 128 + (hg & 1) * 64 + wn * 32;
    #pragma unroll
    for (int nt = 0; nt < 4; ++nt) {
        const int col = colbase + nt * 8 + 2 * (lane & 3);
        const float b0 = bias[col], b1 = bias[col + 1];
        #pragma unroll
        for (int mt = 0; mt < 4; ++mt) {
            const int r0 = t0 + wm * 64 + mt * 16 + (lane >> 2);
            float2 v0 = make_float2(acc[mt][nt][0] + b0, acc[mt][nt][1] + b1);
            float2 v1 = make_float2(acc[mt][nt][2] + b0, acc[mt][nt][3] + b1);
            *(float2*)(out + (size_t)r0 * IN_F + col)       = v0;
            *(float2*)(out + (size_t)(r0 + 8) * IN_F + col) = v1;
        }
    }
}

// ---------------- launch: fork-join chunked overlap of xprep and GEMM ------------
extern "C" void kernel_launch(void* const* d_in, const int* in_sizes, int n_in,
                              void* d_out, int out_size)
{
    const float* x    = (const float*)d_in[0];
    const int*   perm = (const int*)d_in[1];
    const float* W    = (const float*)d_in[2];
    const float* bias = (const float*)d_in[3];
    float* out = (float*)d_out;

    const int T = in_sizes[0] / IN_F;   // 16384
    const int tok_per = T / NCHUNK;     // 2048 tokens per chunk
    const int tt_per  = tok_per / TILE_T;  // 16 token tiles per chunk

    cudaFuncSetAttribute(xprep_kernel,
                         cudaFuncAttributeMaxDynamicSharedMemorySize, 65536);
    cudaFuncSetAttribute(bdl_mma_kernel,
                         cudaFuncAttributeMaxDynamicSharedMemorySize, SM_SZ);

    // prep (stream 0; xprep and GEMM both depend on these)
    convert_perm_kernel<<<1, 1024>>>(perm);
    wprep_kernel<<<64, 256>>>(W);

    // fork a second stream into the capture graph
    cudaStream_t s2;
    cudaStreamCreateWithFlags(&s2, cudaStreamNonBlocking);
    cudaEvent_t efork;
    cudaEventCreateWithFlags(&efork, cudaEventDisableTiming);
    cudaEventRecord(efork, 0);
    cudaStreamWaitEvent(s2, efork, 0);

    // xprep chunks on s2, each followed by an event
    cudaEvent_t ex[NCHUNK];
    for (int c = 0; c < NCHUNK; ++c) {
        cudaEventCreateWithFlags(&ex[c], cudaEventDisableTiming);
        xprep_kernel<<<tok_per / 8, 256, 65536, s2>>>(x, c * tok_per);
        cudaEventRecord(ex[c], s2);
    }

    // GEMM chunks on stream 0, each gated on its xprep chunk; GEMM(c)
    // overlaps xprep(c+1..). Join: every s2 node is an ancestor of a
    // stream-0 node via ex[c].
    for (int c = 0; c < NCHUNK; ++c) {
        cudaStreamWaitEvent(0, ex[c], 0);
        dim3 grid(64, tt_per);
        bdl_mma_kernel<<<grid, 128, SM_SZ>>>(bias, out, c * tt_per);
    }
    // NOTE: stream/event handles intentionally not destroyed here —
    // destroying capture-participating handles mid-capture invalidates the
    // graph. They are host-side objects (no device memory), created fresh
    // per call (deterministic, no caching).
}

// round 16
// speedup vs baseline: 1.3911x; 1.3911x over previous
#include <cuda_runtime.h>
#include <cuda_fp16.h>
#include <cstdint>

// Problem: B=4,S=4096 -> T=16384 tokens; IN_F=OUT_F=4096; G=32; GS=GO=128.
// y[t, g*128+n] = sum_k x[t, perm[g*128+k]] * W[g,n,k] + b[g,n]
// Numerics: x -> fp16, W -> fp16 hi + lo; y = xh*Wh + xh*Wl, f32 accum.
#define IN_F   4096
#define G      32
#define TMAX   16384
#define TILE_T 128
#define NCHUNK 2

// ---------------- device scratch (static; no allocation) ----------------
__device__ int      g_perm[IN_F];
__device__ uint32_t g_whf[64 * 4096];     // W hi fragments per half-group (fp16x2)
__device__ uint32_t g_wlf[64 * 4096];     // W lo fragments (fp16x2)
// Pre-swizzled fp16 A tiles: [ttile=128][g=32][32KB tile]
__device__ unsigned char g_xt[(size_t)128 * 32 * 32768];

__device__ __forceinline__ uint32_t smem_u32(const void* p) {
    uint32_t a;
    asm("{ .reg .u64 t; cvta.to.shared.u64 t, %1; cvt.u32.u64 %0, t; }" : "=r"(a) : "l"(p));
    return a;
}

__device__ __forceinline__ uint32_t pack_h2(float lo, float hi) {
    __half2 h = __floats2half2_rn(lo, hi);   // lo -> low 16 bits
    return *(uint32_t*)&h;
}

// ---------------- pass 0a: normalize perm (int64-or-int32 -> int32) ----------------
__global__ void convert_perm_kernel(const int* __restrict__ p32) {
    __shared__ int is64;
    if (threadIdx.x == 0) {
        int all0 = 1;
        #pragma unroll
        for (int i = 1; i < 16; i += 2) all0 &= (p32[i] == 0);
        is64 = all0;
    }
    __syncthreads();
    const int w = is64;
    for (int i = threadIdx.x; i < IN_F; i += blockDim.x)
        g_perm[i] = w ? p32[2 * i] : p32[i];
}

// ---------------- pass 0b: W -> fp16 hi/lo, LDS.64-friendly fragment order --------
// e = ((((wn*8 + ks)*4 + nt)*32) + lane)*2 + r
//   n  = (hg&1)*64 + wn*32 + nt*8 + lane/4 ; k0 = ks*16 + 2*(lane&3) + r*8
__global__ void wprep_kernel(const float* __restrict__ W) {
    const int hg = blockIdx.x;            // 0..63
    const int g = hg >> 1;
    for (int e = threadIdx.x; e < 4096; e += blockDim.x) {
        const int r    = e & 1;
        const int lane = (e >> 1) & 31;
        const int nt   = (e >> 6) & 3;
        const int ks   = (e >> 8) & 7;
        const int wn   = e >> 11;
        const int n    = (hg & 1) * 64 + wn * 32 + nt * 8 + (lane >> 2);
        const int k0   = ks * 16 + 2 * (lane & 3) + r * 8;
        const float v0 = W[((size_t)g * 128 + n) * 128 + k0];
        const float v1 = W[((size_t)g * 128 + n) * 128 + k0 + 1];
        const float h0 = __half2float(__float2half_rn(v0));
        const float h1 = __half2float(__float2half_rn(v1));
        g_whf[hg * 4096 + e] = pack_h2(h0, h1);
        g_wlf[hg * 4096 + e] = pack_h2(v0 - h0, v1 - h1);
    }
}

// ---------------- pass 1: permute + fp16 convert into GEMM-ready tiles ----------------
// Block: 4 tokens, 256 threads, 32 KB smem (so it can co-reside with the GEMM's
// 3x64KB and actually overlap). Same per-element work as the 8-token version.
__global__ __launch_bounds__(256) void xprep_kernel(const float* __restrict__ x, int tok0) {
    extern __shared__ unsigned short rows16[];      // 4 * 4096 fp16 = 32 KB
    const int t0    = tok0 + blockIdx.x * 4;
    const int ttile = t0 >> 7;
    const int tbase = t0 & 127;
    const int tid = threadIdx.x, lane = tid & 31, wid = tid >> 5;

    {
        const float4* src = (const float4*)(x + (size_t)t0 * IN_F);
        uint2* r2 = (uint2*)rows16;
        #pragma unroll 8
        for (int i = tid; i < 4096; i += 256) {
            const float4 v = src[i];
            r2[i] = make_uint2(pack_h2(v.x, v.y), pack_h2(v.z, v.w));
        }
    }
    __syncthreads();

    const int q       = lane & 15;                  // 16B chunk within row
    const int half_id = wid * 2 + (lane >> 4);      // 0..15

    #pragma unroll 4
    for (int it = 0; it < 8; ++it) {
        const int rt  = it * 16 + half_id;          // 0..127
        const int tok = rt >> 5;                    // 0..3
        const int g   = rt & 31;
        const unsigned short* row = rows16 + tok * IN_F;

        const int4* pp = (const int4*)(g_perm + g * 128 + 8 * q);
        const int4 pa = pp[0];
        const int4 pb = pp[1];

        uint4 v;
        v.x = (uint32_t)row[pa.x] | ((uint32_t)row[pa.y] << 16);
        v.y = (uint32_t)row[pa.z] | ((uint32_t)row[pa.w] << 16);
        v.z = (uint32_t)row[pb.x] | ((uint32_t)row[pb.y] << 16);
        v.w = (uint32_t)row[pb.z] | ((uint32_t)row[pb.w] << 16);

        const uint32_t t   = (uint32_t)(tbase + tok);
        const uint32_t off = t * 256 + (((uint32_t)q ^ (t & 7)) << 4);
        *(uint4*)(g_xt + ((size_t)ttile * 32 + g) * 32768 + off) = v;
    }
}

// ---------------- pass 2: HMMA block-diagonal GEMM, all-smem mainloop ------------
// CTA: 128 tokens x 64 outputs (half-group), 128 threads, warp grid 2x2,
// warp tile 64x32. Prologue cp.asyncs A (32KB) + B hi/lo (32KB); mainloop
// touches ONLY smem (ldmatrix + LDS.64) + HMMA. 3 CTA/SM.
#define SM_A   0
#define SM_BH  32768
#define SM_BL  49152
#define SM_SZ  65536

__global__ __launch_bounds__(128, 3)
void bdl_mma_kernel(const float* __restrict__ bias, float* __restrict__ out, int tt0)
{
    extern __shared__ char smem[];
    const uint32_t sb = smem_u32(smem);
    const int hg = blockIdx.x;
    const int g  = hg >> 1;
    const int ttile = tt0 + blockIdx.y;
    const int t0 = ttile * TILE_T;
    const int tid = threadIdx.x, lane = tid & 31, wid = tid >> 5;

    // --- prologue: A tile + B hi/lo via cp.async, one wait ---
    {
        const unsigned char* sa = g_xt + ((size_t)ttile * 32 + g) * 32768;
        #pragma unroll 4
        for (int e = tid; e < 2048; e += 128)
            asm volatile("cp.async.cg.shared.global [%0], [%1], 16;"
                         :: "r"(sb + SM_A + e * 16), "l"(sa + e * 16));
        const unsigned char* bh = (const unsigned char*)(g_whf + hg * 4096);
        const unsigned char* bl = (const unsigned char*)(g_wlf + hg * 4096);
        #pragma unroll 4
        for (int e = tid; e < 1024; e += 128) {
            asm volatile("cp.async.cg.shared.global [%0], [%1], 16;"
                         :: "r"(sb + SM_BH + e * 16), "l"(bh + e * 16));
            asm volatile("cp.async.cg.shared.global [%0], [%1], 16;"
                         :: "r"(sb + SM_BL + e * 16), "l"(bl + e * 16));
        }
        asm volatile("cp.async.commit_group;");
        asm volatile("cp.async.wait_group 0;");
    }
    __syncthreads();

    const int wm = wid & 1;
    const int wn = wid >> 1;

    const uint32_t bh_base = sb + SM_BH + (uint32_t)wn * 8192 + (uint32_t)lane * 8;
    const uint32_t bl_base = sb + SM_BL + (uint32_t)wn * 8192 + (uint32_t)lane * 8;

    float acc[4][4][4];
    #pragma unroll
    for (int mt = 0; mt < 4; ++mt)
        #pragma unroll
        for (int nt = 0; nt < 4; ++nt)
            #pragma unroll
            for (int q = 0; q < 4; ++q) acc[mt][nt][q] = 0.0f;

    #pragma unroll
    for (int ks = 0; ks < 8; ++ks) {
        uint32_t bh[4][2], bl[4][2];
        #pragma unroll
        for (int nt = 0; nt < 4; ++nt) {
            const uint32_t soff = (uint32_t)(ks * 4 + nt) * 256;
            asm volatile("ld.shared.v2.b32 {%0,%1}, [%2];"
                         : "=r"(bh[nt][0]), "=r"(bh[nt][1]) : "r"(bh_base + soff));
            asm volatile("ld.shared.v2.b32 {%0,%1}, [%2];"
                         : "=r"(bl[nt][0]), "=r"(bl[nt][1]) : "r"(bl_base + soff));
        }

        uint32_t ah[4][4];
        #pragma unroll
        for (int mt = 0; mt < 4; ++mt) {
            const uint32_t row = (uint32_t)(wm * 64 + mt * 16 + (lane & 15));
            const uint32_t c   = (uint32_t)(2 * ks + (lane >> 4));
            const uint32_t aoff = row * 256 + ((c ^ (row & 7)) << 4);
            asm volatile("ldmatrix.sync.aligned.m8n8.x4.shared.b16 {%0,%1,%2,%3}, [%4];"
                         : "=r"(ah[mt][0]), "=r"(ah[mt][1]), "=r"(ah[mt][2]), "=r"(ah[mt][3])
                         : "r"(sb + SM_A + aoff));
        }
        #pragma unroll
        for (int mt = 0; mt < 4; ++mt)
            #pragma unroll
            for (int nt = 0; nt < 4; ++nt) {
                asm volatile(
                    "mma.sync.aligned.m16n8k16.row.col.f32.f16.f16.f32 "
                    "{%0,%1,%2,%3}, {%4,%5,%6,%7}, {%8,%9}, {%0,%1,%2,%3};"
                    : "+f"(acc[mt][nt][0]), "+f"(acc[mt][nt][1]),
                      "+f"(acc[mt][nt][2]), "+f"(acc[mt][nt][3])
                    : "r"(ah[mt][0]), "r"(ah[mt][1]), "r"(ah[mt][2]), "r"(ah[mt][3]),
                      "r"(bh[nt][0]), "r"(bh[nt][1]));
                asm volatile(
                    "mma.sync.aligned.m16n8k16.row.col.f32.f16.f16.f32 "
                    "{%0,%1,%2,%3}, {%4,%5,%6,%7}, {%8,%9}, {%0,%1,%2,%3};"
                    : "+f"(acc[mt][nt][0]), "+f"(acc[mt][nt][1]),
                      "+f"(acc[mt][nt][2]), "+f"(acc[mt][nt][3])
                    : "r"(ah[mt][0]), "r"(ah[mt][1]), "r"(ah[mt][2]), "r"(ah[mt][3]),
                      "r"(bl[nt][0]), "r"(bl[nt][1]));
            }
    }

    // --- epilogue: bias + st.v2 (c-fragment layout) ---
    const int colbase = g * 128 + (hg & 1) * 64 + wn * 32;
    #pragma unroll
    for (int nt = 0; nt < 4; ++nt) {
        const int col = colbase + nt * 8 + 2 * (lane & 3);
        const float b0 = bias[col], b1 = bias[col + 1];
        #pragma unroll
        for (int mt = 0; mt < 4; ++mt) {
            const int r0 = t0 + wm * 64 + mt * 16 + (lane >> 2);
            float2 v0 = make_float2(acc[mt][nt][0] + b0, acc[mt][nt][1] + b1);
            float2 v1 = make_float2(acc[mt][nt][2] + b0, acc[mt][nt][3] + b1);
            *(float2*)(out + (size_t)r0 * IN_F + col)       = v0;
            *(float2*)(out + (size_t)(r0 + 8) * IN_F + col) = v1;
        }
    }
}

// ---------------- launch: 2-chunk fork-join overlap (xprep(1) || GEMM(0)) --------
extern "C" void kernel_launch(void* const* d_in, const int* in_sizes, int n_in,
                              void* d_out, int out_size)
{
    const float* x    = (const float*)d_in[0];
    const int*   perm = (const int*)d_in[1];
    const float* W    = (const float*)d_in[2];
    const float* bias = (const float*)d_in[3];
    float* out = (float*)d_out;

    const int T = in_sizes[0] / IN_F;        // 16384
    const int tok_per = T / NCHUNK;          // 8192 tokens per chunk
    const int tt_per  = tok_per / TILE_T;    // 64 token tiles per chunk

    cudaFuncSetAttribute(xprep_kernel,
                         cudaFuncAttributeMaxDynamicSharedMemorySize, 32768);
    cudaFuncSetAttribute(bdl_mma_kernel,
                         cudaFuncAttributeMaxDynamicSharedMemorySize, SM_SZ);

    // prep (stream 0)
    convert_perm_kernel<<<1, 1024>>>(perm);
    wprep_kernel<<<64, 256>>>(W);

    // fork a second stream into the capture graph
    cudaStream_t s2;
    cudaStreamCreateWithFlags(&s2, cudaStreamNonBlocking);
    cudaEvent_t efork;
    cudaEventCreateWithFlags(&efork, cudaEventDisableTiming);
    cudaEventRecord(efork, 0);
    cudaStreamWaitEvent(s2, efork, 0);

    // xprep chunks on s2 (32KB blocks -> can co-reside with GEMM's 3x64KB)
    cudaEvent_t ex[NCHUNK];
    for (int c = 0; c < NCHUNK; ++c) {
        cudaEventCreateWithFlags(&ex[c], cudaEventDisableTiming);
        xprep_kernel<<<tok_per / 4, 256, 32768, s2>>>(x, c * tok_per);
        cudaEventRecord(ex[c], s2);
    }

    // GEMM chunks on stream 0; GEMM(0) overlaps xprep(1). Join via ex[c].
    for (int c = 0; c < NCHUNK; ++c) {
        cudaStreamWaitEvent(0, ex[c], 0);
        dim3 grid(64, tt_per);
        bdl_mma_kernel<<<grid, 128, SM_SZ>>>(bias, out, c * tt_per);
    }
    // Stream/event handles intentionally not destroyed (capture-participating
    // host objects; no device memory; created fresh per call).
}

// round 17
// speedup vs baseline: 1.6410x; 1.1796x over previous
#include <cuda_runtime.h>
#include <cuda_fp16.h>
#include <cstdint>

// Problem: B=4,S=4096 -> T=16384 tokens; IN_F=OUT_F=4096; G=32; GS=GO=128.
// y[t, g*128+n] = sum_k x[t, perm[g*128+k]] * W[g,n,k] + b[g,n]
// Numerics: x -> fp16 and W -> fp16 (each ~2^-12 rel RMS), f32 accum.
// Combined norm rel err ~3e-4 < 1e-3 threshold.
#define IN_F   4096
#define G      32
#define TMAX   16384
#define TILE_T 128

// ---------------- device scratch (static; no allocation) ----------------
__device__ int      g_perm[IN_F];
__device__ uint32_t g_whf[64 * 4096];     // W fp16 fragments per half-group (fp16x2)
// Pre-swizzled fp16 A tiles: [ttile=128][g=32][32KB tile]
__device__ unsigned char g_xt[(size_t)128 * 32 * 32768];

__device__ __forceinline__ uint32_t smem_u32(const void* p) {
    uint32_t a;
    asm("{ .reg .u64 t; cvta.to.shared.u64 t, %1; cvt.u32.u64 %0, t; }" : "=r"(a) : "l"(p));
    return a;
}

__device__ __forceinline__ uint32_t pack_h2(float lo, float hi) {
    __half2 h = __floats2half2_rn(lo, hi);   // lo -> low 16 bits
    return *(uint32_t*)&h;
}

// ---------------- pass 0a: normalize perm (int64-or-int32 -> int32) ----------------
__global__ void convert_perm_kernel(const int* __restrict__ p32) {
    __shared__ int is64;
    if (threadIdx.x == 0) {
        int all0 = 1;
        #pragma unroll
        for (int i = 1; i < 16; i += 2) all0 &= (p32[i] == 0);
        is64 = all0;
    }
    __syncthreads();
    const int w = is64;
    for (int i = threadIdx.x; i < IN_F; i += blockDim.x)
        g_perm[i] = w ? p32[2 * i] : p32[i];
}

// ---------------- pass 0b: W -> fp16, LDS.64-friendly fragment order --------
// e = ((((wn*8 + ks)*4 + nt)*32) + lane)*2 + r
//   n  = (hg&1)*64 + wn*32 + nt*8 + lane/4 ; k0 = ks*16 + 2*(lane&3) + r*8
// Per (wn,ks,nt): 64 consecutive u32 across lanes -> conflict-free ld.shared.v2.
__global__ void wprep_kernel(const float* __restrict__ W) {
    const int hg = blockIdx.x;            // 0..63
    const int g = hg >> 1;
    for (int e = threadIdx.x; e < 4096; e += blockDim.x) {
        const int r    = e & 1;
        const int lane = (e >> 1) & 31;
        const int nt   = (e >> 6) & 3;
        const int ks   = (e >> 8) & 7;
        const int wn   = e >> 11;
        const int n    = (hg & 1) * 64 + wn * 32 + nt * 8 + (lane >> 2);
        const int k0   = ks * 16 + 2 * (lane & 3) + r * 8;
        const float v0 = W[((size_t)g * 128 + n) * 128 + k0];
        const float v1 = W[((size_t)g * 128 + n) * 128 + k0 + 1];
        g_whf[hg * 4096 + e] = pack_h2(v0, v1);
    }
}

// ---------------- pass 1: permute + fp16 convert into GEMM-ready tiles ----------------
// Block: 8 tokens, 256 threads, 64 KB smem fp16 rows. (R14 version, monolithic.)
__global__ __launch_bounds__(256) void xprep_kernel(const float* __restrict__ x) {
    extern __shared__ unsigned short rows16[];      // 8 * 4096 fp16 = 64 KB
    const int t0    = blockIdx.x * 8;
    const int ttile = t0 >> 7;
    const int tbase = t0 & 127;
    const int tid = threadIdx.x, lane = tid & 31, wid = tid >> 5;

    {
        const float4* src = (const float4*)(x + (size_t)t0 * IN_F);
        uint2* r2 = (uint2*)rows16;
        #pragma unroll 8
        for (int i = tid; i < 8192; i += 256) {
            const float4 v = src[i];
            r2[i] = make_uint2(pack_h2(v.x, v.y), pack_h2(v.z, v.w));
        }
    }
    __syncthreads();

    const int q       = lane & 15;                  // 16B chunk within row
    const int half_id = wid * 2 + (lane >> 4);      // 0..15

    #pragma unroll 4
    for (int it = 0; it < 16; ++it) {
        const int rt  = it * 16 + half_id;          // 0..255
        const int tok = rt >> 5;                    // 0..7
        const int g   = rt & 31;
        const unsigned short* row = rows16 + tok * IN_F;

        const int4* pp = (const int4*)(g_perm + g * 128 + 8 * q);
        const int4 pa = pp[0];
        const int4 pb = pp[1];

        uint4 v;
        v.x = (uint32_t)row[pa.x] | ((uint32_t)row[pa.y] << 16);
        v.y = (uint32_t)row[pa.z] | ((uint32_t)row[pa.w] << 16);
        v.z = (uint32_t)row[pb.x] | ((uint32_t)row[pb.y] << 16);
        v.w = (uint32_t)row[pb.z] | ((uint32_t)row[pb.w] << 16);

        const uint32_t t   = (uint32_t)(tbase + tok);
        const uint32_t off = t * 256 + (((uint32_t)q ^ (t & 7)) << 4);
        *(uint4*)(g_xt + ((size_t)ttile * 32 + g) * 32768 + off) = v;
    }
}

// ---------------- pass 2: HMMA block-diagonal GEMM, single product -------------
// CTA: 128 tokens x 64 outputs (half-group), 128 threads, warp grid 2x2,
// warp tile 64x32. Prologue cp.asyncs A (32KB) + B (16KB); mainloop touches
// ONLY smem (ldmatrix + LDS.64) + HMMA. 48KB smem -> 4 CTA/SM, 16 warps/SM.
#define SM_A   0
#define SM_BH  32768
#define SM_SZ  49152

__global__ __launch_bounds__(128, 4)
void bdl_mma_kernel(const float* __restrict__ bias, float* __restrict__ out)
{
    extern __shared__ char smem[];
    const uint32_t sb = smem_u32(smem);
    const int hg = blockIdx.x;
    const int g  = hg >> 1;
    const int t0 = blockIdx.y * TILE_T;
    const int tid = threadIdx.x, lane = tid & 31, wid = tid >> 5;

    // --- prologue: A tile + B via cp.async, one wait ---
    {
        const unsigned char* sa = g_xt + ((size_t)blockIdx.y * 32 + g) * 32768;
        #pragma unroll 4
        for (int e = tid; e < 2048; e += 128)
            asm volatile("cp.async.cg.shared.global [%0], [%1], 16;"
                         :: "r"(sb + SM_A + e * 16), "l"(sa + e * 16));
        const unsigned char* bh = (const unsigned char*)(g_whf + hg * 4096);
        #pragma unroll 4
        for (int e = tid; e < 1024; e += 128)
            asm volatile("cp.async.cg.shared.global [%0], [%1], 16;"
                         :: "r"(sb + SM_BH + e * 16), "l"(bh + e * 16));
        asm volatile("cp.async.commit_group;");
        asm volatile("cp.async.wait_group 0;");
    }
    __syncthreads();

    const int wm = wid & 1;
    const int wn = wid >> 1;

    const uint32_t bh_base = sb + SM_BH + (uint32_t)wn * 8192 + (uint32_t)lane * 8;

    float acc[4][4][4];
    #pragma unroll
    for (int mt = 0; mt < 4; ++mt)
        #pragma unroll
        for (int nt = 0; nt < 4; ++nt)
            #pragma unroll
            for (int q = 0; q < 4; ++q) acc[mt][nt][q] = 0.0f;

    #pragma unroll
    for (int ks = 0; ks < 8; ++ks) {
        uint32_t bh[4][2];
        #pragma unroll
        for (int nt = 0; nt < 4; ++nt) {
            const uint32_t soff = (uint32_t)(ks * 4 + nt) * 256;
            asm volatile("ld.shared.v2.b32 {%0,%1}, [%2];"
                         : "=r"(bh[nt][0]), "=r"(bh[nt][1]) : "r"(bh_base + soff));
        }

        uint32_t ah[4][4];
        #pragma unroll
        for (int mt = 0; mt < 4; ++mt) {
            const uint32_t row = (uint32_t)(wm * 64 + mt * 16 + (lane & 15));
            const uint32_t c   = (uint32_t)(2 * ks + (lane >> 4));
            const uint32_t aoff = row * 256 + ((c ^ (row & 7)) << 4);
            asm volatile("ldmatrix.sync.aligned.m8n8.x4.shared.b16 {%0,%1,%2,%3}, [%4];"
                         : "=r"(ah[mt][0]), "=r"(ah[mt][1]), "=r"(ah[mt][2]), "=r"(ah[mt][3])
                         : "r"(sb + SM_A + aoff));
        }
        #pragma unroll
        for (int mt = 0; mt < 4; ++mt)
            #pragma unroll
            for (int nt = 0; nt < 4; ++nt) {
                asm volatile(
                    "mma.sync.aligned.m16n8k16.row.col.f32.f16.f16.f32 "
                    "{%0,%1,%2,%3}, {%4,%5,%6,%7}, {%8,%9}, {%0,%1,%2,%3};"
                    : "+f"(acc[mt][nt][0]), "+f"(acc[mt][nt][1]),
                      "+f"(acc[mt][nt][2]), "+f"(acc[mt][nt][3])
                    : "r"(ah[mt][0]), "r"(ah[mt][1]), "r"(ah[mt][2]), "r"(ah[mt][3]),
                      "r"(bh[nt][0]), "r"(bh[nt][1]));
            }
    }

    // --- epilogue: bias + st.v2 (c-fragment layout) ---
    const int colbase = g * 128 + (hg & 1) * 64 + wn * 32;
    #pragma unroll
    for (int nt = 0; nt < 4; ++nt) {
        const int col = colbase + nt * 8 + 2 * (lane & 3);
        const float b0 = bias[col], b1 = bias[col + 1];
        #pragma unroll
        for (int mt = 0; mt < 4; ++mt) {
            const int r0 = t0 + wm * 64 + mt * 16 + (lane >> 2);
            float2 v0 = make_float2(acc[mt][nt][0] + b0, acc[mt][nt][1] + b1);
            float2 v1 = make_float2(acc[mt][nt][2] + b0, acc[mt][nt][3] + b1);
            *(float2*)(out + (size_t)r0 * IN_F + col)       = v0;
            *(float2*)(out + (size_t)(r0 + 8) * IN_F + col) = v1;
        }
    }
}

// ---------------- launch (serial; overlap demonstrated not to help) --------------
extern "C" void kernel_launch(void* const* d_in, const int* in_sizes, int n_in,
                              void* d_out, int out_size)
{
    const float* x    = (const float*)d_in[0];
    const int*   perm = (const int*)d_in[1];
    const float* W    = (const float*)d_in[2];
    const float* bias = (const float*)d_in[3];
    float* out = (float*)d_out;

    const int T = in_sizes[0] / IN_F;   // 16384

    convert_perm_kernel<<<1, 1024>>>(perm);
    wprep_kernel<<<64, 256>>>(W);

    cudaFuncSetAttribute(xprep_kernel,
                         cudaFuncAttributeMaxDynamicSharedMemorySize, 65536);
    xprep_kernel<<<T / 8, 256, 65536>>>(x);

    cudaFuncSetAttribute(bdl_mma_kernel,
                         cudaFuncAttributeMaxDynamicSharedMemorySize, SM_SZ);
    dim3 grid(64, T / TILE_T);          // (64 half-groups, 128 token tiles)
    bdl_mma_kernel<<<grid, 128, SM_SZ>>>(bias, out);
}